// round 12
// baseline (speedup 1.0000x reference)
#include <cuda_runtime.h>

// Problem constants
#define TPB    320        // 32000/320 = 100 blocks per d; 10 warps, 1 block/SM
#define NSAMP  32000      // B*length = 32*1000
#define LEN    1000
#define TROW   1002
#define DDIM   16
#define EDIM   32
#define HDIM   64

typedef unsigned long long u64;

// Packed fp32x2 FMA (Blackwell sm_10x): d = a*b + c on two packed fp32 lanes.
__device__ __forceinline__ u64 ffma2(u64 a, u64 b, u64 c) {
    u64 d;
    asm("fma.rn.f32x2 %0, %1, %2, %3;" : "=l"(d) : "l"(a), "l"(b), "l"(c));
    return d;
}
__device__ __forceinline__ float hsum2(u64 v) {
    float lo, hi;
    asm("mov.b64 {%0, %1}, %2;" : "=f"(lo), "=f"(hi) : "l"(v));
    return lo + hi;
}
__device__ __forceinline__ u64 pack2(float lo, float hi) {
    u64 v;
    asm("mov.b64 %0, {%1, %2};" : "=l"(v) : "f"(lo), "f"(hi));
    return v;
}

// Scratch for per-(d, n) log|dJ| — deterministic reduction in a second kernel.
__device__ float g_dj[DDIM * NSAMP];

// Dynamic shared memory layout (float offsets):
//   stageA : u64[32 * TPB]   floats [0,      20480)
//   stageT : u64[32 * TPB]   floats [20480,  40960)
//   sW1    : 64x64           [40960, 45056)
//   sW2    : 64x64           [45056, 49152)
//   sW0e   : 64x32           [49152, 51200)
//   sW0x/sWo/sB0/sB1/sB2 : 5x64  [51200, 51520)
#define SMEM_FLOATS 51520
#define SMEM_BYTES  (SMEM_FLOATS * 4)   // 206080 B, single block/SM

// One hidden layer (64x64): 4 output rows per group, a+t co-computed.
// Inner loop: 4x LDS.128 + 16x ffma2  (1:4 — fma-pipe bound).
__device__ __forceinline__ void layer64(const float* __restrict__ sW,
                                        const float* __restrict__ sB,
                                        u64* __restrict__ stageA,
                                        u64* __restrict__ stageT,
                                        u64* __restrict__ apk,
                                        u64* __restrict__ tpk,
                                        int tid)
{
#pragma unroll 1
    for (int i = 0; i < HDIM; i += 4) {
        u64 aa0 = 0, aa1 = 0, aa2 = 0, aa3 = 0;
        u64 at0 = 0, at1 = 0, at2 = 0, at3 = 0;
        const ulonglong2* r0 = (const ulonglong2*)(sW + (i + 0) * HDIM);
        const ulonglong2* r1 = (const ulonglong2*)(sW + (i + 1) * HDIM);
        const ulonglong2* r2 = (const ulonglong2*)(sW + (i + 2) * HDIM);
        const ulonglong2* r3 = (const ulonglong2*)(sW + (i + 3) * HDIM);
#pragma unroll
        for (int k = 0; k < 16; ++k) {
            ulonglong2 w0 = r0[k], w1 = r1[k], w2 = r2[k], w3 = r3[k];
            u64 a0 = apk[2 * k], a1 = apk[2 * k + 1];
            u64 t0 = tpk[2 * k], t1 = tpk[2 * k + 1];
            aa0 = ffma2(w0.x, a0, aa0);
            aa1 = ffma2(w1.x, a0, aa1);
            aa2 = ffma2(w2.x, a0, aa2);
            aa3 = ffma2(w3.x, a0, aa3);
            at0 = ffma2(w0.x, t0, at0);
            at1 = ffma2(w1.x, t0, at1);
            at2 = ffma2(w2.x, t0, at2);
            at3 = ffma2(w3.x, t0, at3);
            aa0 = ffma2(w0.y, a1, aa0);
            aa1 = ffma2(w1.y, a1, aa1);
            aa2 = ffma2(w2.y, a1, aa2);
            aa3 = ffma2(w3.y, a1, aa3);
            at0 = ffma2(w0.y, t1, at0);
            at1 = ffma2(w1.y, t1, at1);
            at2 = ffma2(w2.y, t1, at2);
            at3 = ffma2(w3.y, t1, at3);
        }
        float z0 = hsum2(aa0) + sB[i + 0];
        float z1 = hsum2(aa1) + sB[i + 1];
        float z2 = hsum2(aa2) + sB[i + 2];
        float z3 = hsum2(aa3) + sB[i + 3];
        float g0 = (z0 >= 0.f) ? 1.f : 0.2f;
        float g1 = (z1 >= 0.f) ? 1.f : 0.2f;
        float g2 = (z2 >= 0.f) ? 1.f : 0.2f;
        float g3 = (z3 >= 0.f) ? 1.f : 0.2f;
        stageA[((i >> 1) + 0) * TPB + tid] = pack2(z0 * g0, z1 * g1);
        stageA[((i >> 1) + 1) * TPB + tid] = pack2(z2 * g2, z3 * g3);
        stageT[((i >> 1) + 0) * TPB + tid] = pack2(g0 * hsum2(at0), g1 * hsum2(at1));
        stageT[((i >> 1) + 1) * TPB + tid] = pack2(g2 * hsum2(at2), g3 * hsum2(at3));
    }
#pragma unroll
    for (int p = 0; p < 32; ++p) {
        apk[p] = stageA[p * TPB + tid];
        tpk[p] = stageT[p * TPB + tid];
    }
}

extern "C" __global__ void __launch_bounds__(TPB)
mlp_fwd_kernel(const float* __restrict__ x,  const float* __restrict__ emb,
               const float* __restrict__ W0, const float* __restrict__ b0,
               const float* __restrict__ W1, const float* __restrict__ b1,
               const float* __restrict__ W2, const float* __restrict__ b2,
               const float* __restrict__ Wo, const float* __restrict__ bo,
               float* __restrict__ out)
{
    extern __shared__ float smem[];
    const int tid = threadIdx.x;
    const int d   = blockIdx.y;

    u64*   stageA = (u64*)smem;
    u64*   stageT = stageA + 32 * TPB;
    float* sW1    = smem + 40960;
    float* sW2    = sW1 + 4096;
    float* sW0e   = sW2 + 4096;
    float* sW0x   = sW0e + 2048;
    float* sWo    = sW0x + 64;
    float* sB0    = sWo + 64;
    float* sB1    = sB0 + 64;
    float* sB2    = sB1 + 64;

    // ---- cooperative weight staging ----
    {
        const float4* g1 = (const float4*)(W1 + d * 4096);
        const float4* g2 = (const float4*)(W2 + d * 4096);
        float4* s1 = (float4*)sW1;
        float4* s2 = (float4*)sW2;
#pragma unroll 1
        for (int k = tid; k < 1024; k += TPB) {
            s1[k] = g1[k];
            s2[k] = g2[k];
        }
        const float* g0 = W0 + d * HDIM * (EDIM + 1);
#pragma unroll 1
        for (int idx = tid; idx < HDIM * (EDIM + 1); idx += TPB) {
            int h = idx / 33, e = idx - h * 33;
            float v = g0[idx];
            if (e == 32) sW0x[h] = v; else sW0e[h * EDIM + e] = v;
        }
        if (tid < HDIM) {
            sWo[tid] = Wo[d * HDIM + tid];
            sB0[tid] = b0[d * HDIM + tid];
            sB1[tid] = b1[d * HDIM + tid];
            sB2[tid] = b2[d * HDIM + tid];
        }
    }
    __syncthreads();

    const int n   = blockIdx.x * TPB + tid;     // grid.x*TPB == NSAMP exactly
    const int b   = n / LEN;
    const int l   = n - b * LEN;
    const int row = b * TROW + 2 + l;           // LAGS = 2
    const float xt = x[row * DDIM + d];

    // Pack the 32-wide embedding into 16 f32x2 regs.
    u64 epk[16];
    {
        const float4* er = (const float4*)(emb + (size_t)row * EDIM);
#pragma unroll
        for (int k = 0; k < 8; ++k) {
            float4 v = er[k];
            epk[2 * k]     = pack2(v.x, v.y);
            epk[2 * k + 1] = pack2(v.z, v.w);
        }
    }

    // ---- layer 0: z0 = W0e @ emb + W0x * x + b0 ; t0 = g0 * W0x ----
#pragma unroll 1
    for (int i = 0; i < HDIM; i += 4) {
        u64 acc0 = 0, acc1 = 0, acc2 = 0, acc3 = 0;
        const ulonglong2* r0 = (const ulonglong2*)(sW0e + (i + 0) * EDIM);
        const ulonglong2* r1 = (const ulonglong2*)(sW0e + (i + 1) * EDIM);
        const ulonglong2* r2 = (const ulonglong2*)(sW0e + (i + 2) * EDIM);
        const ulonglong2* r3 = (const ulonglong2*)(sW0e + (i + 3) * EDIM);
#pragma unroll
        for (int k = 0; k < 8; ++k) {
            ulonglong2 w0 = r0[k], w1 = r1[k], w2 = r2[k], w3 = r3[k];
            u64 e0 = epk[2 * k], e1 = epk[2 * k + 1];
            acc0 = ffma2(w0.x, e0, acc0);
            acc1 = ffma2(w1.x, e0, acc1);
            acc2 = ffma2(w2.x, e0, acc2);
            acc3 = ffma2(w3.x, e0, acc3);
            acc0 = ffma2(w0.y, e1, acc0);
            acc1 = ffma2(w1.y, e1, acc1);
            acc2 = ffma2(w2.y, e1, acc2);
            acc3 = ffma2(w3.y, e1, acc3);
        }
        float wx0 = sW0x[i + 0], wx1 = sW0x[i + 1];
        float wx2 = sW0x[i + 2], wx3 = sW0x[i + 3];
        float z0 = hsum2(acc0) + wx0 * xt + sB0[i + 0];
        float z1 = hsum2(acc1) + wx1 * xt + sB0[i + 1];
        float z2 = hsum2(acc2) + wx2 * xt + sB0[i + 2];
        float z3 = hsum2(acc3) + wx3 * xt + sB0[i + 3];
        float g0 = (z0 >= 0.f) ? 1.f : 0.2f;
        float g1 = (z1 >= 0.f) ? 1.f : 0.2f;
        float g2 = (z2 >= 0.f) ? 1.f : 0.2f;
        float g3 = (z3 >= 0.f) ? 1.f : 0.2f;
        stageA[((i >> 1) + 0) * TPB + tid] = pack2(z0 * g0, z1 * g1);
        stageA[((i >> 1) + 1) * TPB + tid] = pack2(z2 * g2, z3 * g3);
        stageT[((i >> 1) + 0) * TPB + tid] = pack2(g0 * wx0, g1 * wx1);
        stageT[((i >> 1) + 1) * TPB + tid] = pack2(g2 * wx2, g3 * wx3);
    }

    u64 apk[32], tpk[32];
#pragma unroll
    for (int p = 0; p < 32; ++p) {
        apk[p] = stageA[p * TPB + tid];
        tpk[p] = stageT[p * TPB + tid];
    }

    // ---- layers 1 and 2 ----
    layer64(sW1, sB1, stageA, stageT, apk, tpk, tid);
    layer64(sW2, sB2, stageA, stageT, apk, tpk, tid);

    // ---- output head: res = Wo@a2 + bo ; dJ = Wo@t2 ----
    u64 ra = 0, rt = 0;
    const ulonglong2* wo = (const ulonglong2*)sWo;
#pragma unroll
    for (int k = 0; k < 16; ++k) {
        ulonglong2 w = wo[k];
        ra = ffma2(w.x, apk[2 * k],     ra);
        rt = ffma2(w.x, tpk[2 * k],     rt);
        ra = ffma2(w.y, apk[2 * k + 1], ra);
        rt = ffma2(w.y, tpk[2 * k + 1], rt);
    }
    out[n * DDIM + d] = hsum2(ra) + bo[d];
    g_dj[d * NSAMP + n] = logf(fabsf(hsum2(rt)));
}

extern "C" __global__ void __launch_bounds__(256)
reduce_logdet_kernel(float* __restrict__ out)
{
    int n = blockIdx.x * 256 + threadIdx.x;
    if (n < NSAMP) {
        float s = 0.f;
#pragma unroll
        for (int d = 0; d < DDIM; ++d) s += g_dj[d * NSAMP + n];
        out[NSAMP * DDIM + n] = s;   // logdet region after residuals
    }
}

extern "C" void kernel_launch(void* const* d_in, const int* in_sizes, int n_in,
                              void* d_out, int out_size)
{
    const float* x   = (const float*)d_in[0];
    const float* emb = (const float*)d_in[1];
    const float* W0  = (const float*)d_in[2];
    const float* b0  = (const float*)d_in[3];
    const float* W1  = (const float*)d_in[4];
    const float* b1  = (const float*)d_in[5];
    const float* W2  = (const float*)d_in[6];
    const float* b2  = (const float*)d_in[7];
    const float* Wo  = (const float*)d_in[8];
    const float* bo  = (const float*)d_in[9];
    float* out = (float*)d_out;

    // Idempotent opt-in for >48KB dynamic smem (capture-safe, not a stream op).
    cudaFuncSetAttribute(mlp_fwd_kernel,
                         cudaFuncAttributeMaxDynamicSharedMemorySize, SMEM_BYTES);

    dim3 grid(NSAMP / TPB, DDIM);   // (100, 16)
    mlp_fwd_kernel<<<grid, TPB, SMEM_BYTES>>>(x, emb, W0, b0, W1, b1, W2, b2,
                                              Wo, bo, out);
    reduce_logdet_kernel<<<(NSAMP + 255) / 256, 256>>>(out);
}

// round 14
// speedup vs baseline: 3.4123x; 3.4123x over previous
#include <cuda_runtime.h>
#include <cuda_bf16.h>

// Problem constants
#define TPB    256        // 8 warps; one 16-row m-tile per warp; 128 samples/CTA
#define NSAMP  32000      // B*length = 32*1000
#define LEN    1000
#define TROW   1002
#define DDIM   16
#define EDIM   32
#define HDIM   64

typedef unsigned int u32;

// Scratch for per-(d, n) log|dJ| — deterministic reduction in a second kernel.
__device__ float g_dj[DDIM * NSAMP];

// ---------------- smem layout (byte offsets) ----------------
// A0hi [128][56] bf16, A0lo same     (layer-0 input rows, padded stride 56)
// W0hi/lo [64][48] bf16              (layer-0 weights, k 0..32 used, rest 0)
// W1hi/lo, W2hi/lo [64][72] bf16     (hidden weights, padded stride 72)
// f32: W0x[64], Wo[64], b0[64], b1[64], b2[64]
#define OFF_A0HI 0
#define OFF_A0LO 14336
#define OFF_W0HI 28672
#define OFF_W0LO 34816
#define OFF_W1HI 40960
#define OFF_W1LO 50176
#define OFF_W2HI 59392
#define OFF_W2LO 68608
#define OFF_F32  77824
#define SMEM_BYTES 79104   // x2 CTAs = 158208 <= 228KB

#define A0_STRIDE 56       // 112B rows: 28-word stride -> conflict-free frag LDS
#define W0_STRIDE 48       // 96B rows (2-way on B LDS, layer0 only — acceptable)
#define W_STRIDE  72       // 144B rows: 36-word stride -> conflict-free B LDS

// pack two f32 into bf16x2 (v0 -> low half, v1 -> high half)
__device__ __forceinline__ u32 cvtbf2(float v0, float v1) {
    u32 v; asm("cvt.rn.bf16x2.f32 %0, %1, %2;" : "=r"(v) : "f"(v1), "f"(v0)); return v;
}
__device__ __forceinline__ float lo_f(u32 p) { return __uint_as_float(p << 16); }
__device__ __forceinline__ float hi_f(u32 p) { return __uint_as_float(p & 0xffff0000u); }

// split v0,v1 into bf16 hi pair + bf16 lo (residual) pair
__device__ __forceinline__ void pack_hilo(float v0, float v1, u32& h, u32& l) {
    h = cvtbf2(v0, v1);
    l = cvtbf2(v0 - lo_f(h), v1 - hi_f(h));
}

__device__ __forceinline__ void mma16816(float c[4], const u32 a[4], u32 b0, u32 b1) {
    asm volatile(
        "mma.sync.aligned.m16n8k16.row.col.f32.bf16.bf16.f32 "
        "{%0,%1,%2,%3}, {%4,%5,%6,%7}, {%8,%9}, {%0,%1,%2,%3};"
        : "+f"(c[0]), "+f"(c[1]), "+f"(c[2]), "+f"(c[3])
        : "r"(a[0]), "r"(a[1]), "r"(a[2]), "r"(a[3]), "r"(b0), "r"(b1));
}

// One hidden 64x64 layer: C[8 n-tiles][4] = (Ahi+Alo) @ (Whi+Wlo), 3-way split.
__device__ __forceinline__ void hidden_mma(const __nv_bfloat16* __restrict__ Whi,
                                           const __nv_bfloat16* __restrict__ Wlo,
                                           int q, int r,
                                           const u32 ah[4][4], const u32 al[4][4],
                                           float c[8][4])
{
#pragma unroll
    for (int nt = 0; nt < 8; ++nt)
#pragma unroll
        for (int i = 0; i < 4; ++i) c[nt][i] = 0.f;
#pragma unroll
    for (int kt = 0; kt < 4; ++kt) {
#pragma unroll
        for (int nt = 0; nt < 8; ++nt) {
            const __nv_bfloat16* bh = Whi + (8 * nt + q) * W_STRIDE + 16 * kt + 2 * r;
            const __nv_bfloat16* bl = Wlo + (8 * nt + q) * W_STRIDE + 16 * kt + 2 * r;
            u32 bh0 = *(const u32*)bh, bh1 = *(const u32*)(bh + 8);
            u32 bl0 = *(const u32*)bl, bl1 = *(const u32*)(bl + 8);
            mma16816(c[nt], ah[kt], bh0, bh1);
            mma16816(c[nt], ah[kt], bl0, bl1);
            mma16816(c[nt], al[kt], bh0, bh1);
        }
    }
}

extern "C" __global__ void __launch_bounds__(TPB, 2)
mlp_mma_kernel(const float* __restrict__ x,  const float* __restrict__ emb,
               const float* __restrict__ W0, const float* __restrict__ b0,
               const float* __restrict__ W1, const float* __restrict__ b1,
               const float* __restrict__ W2, const float* __restrict__ b2,
               const float* __restrict__ Wo, const float* __restrict__ bo,
               float* __restrict__ out)
{
    extern __shared__ char smraw[];
    __nv_bfloat16* A0hi = (__nv_bfloat16*)(smraw + OFF_A0HI);
    __nv_bfloat16* A0lo = (__nv_bfloat16*)(smraw + OFF_A0LO);
    __nv_bfloat16* W0hi = (__nv_bfloat16*)(smraw + OFF_W0HI);
    __nv_bfloat16* W0lo = (__nv_bfloat16*)(smraw + OFF_W0LO);
    __nv_bfloat16* W1hi = (__nv_bfloat16*)(smraw + OFF_W1HI);
    __nv_bfloat16* W1lo = (__nv_bfloat16*)(smraw + OFF_W1LO);
    __nv_bfloat16* W2hi = (__nv_bfloat16*)(smraw + OFF_W2HI);
    __nv_bfloat16* W2lo = (__nv_bfloat16*)(smraw + OFF_W2LO);
    float* sF   = (float*)(smraw + OFF_F32);
    float* sW0x = sF;
    float* sWo  = sF + 64;
    float* sB0  = sF + 128;
    float* sB1  = sF + 192;
    float* sB2  = sF + 256;

    const int tid   = threadIdx.x;
    const int d     = blockIdx.y;
    const int nbase = blockIdx.x * 128;

    // ---- stage W1, W2 (split bf16 hi/lo, [n][k] row-major padded) ----
    {
        const float* g1 = W1 + d * 4096;
        const float* g2 = W2 + d * 4096;
#pragma unroll 1
        for (int idx = tid; idx < 4096; idx += TPB) {
            int n = idx >> 6, k = idx & 63;
            float v1 = g1[idx];
            __nv_bfloat16 h1 = __float2bfloat16(v1);
            W1hi[n * W_STRIDE + k] = h1;
            W1lo[n * W_STRIDE + k] = __float2bfloat16(v1 - __bfloat162float(h1));
            float v2 = g2[idx];
            __nv_bfloat16 h2 = __float2bfloat16(v2);
            W2hi[n * W_STRIDE + k] = h2;
            W2lo[n * W_STRIDE + k] = __float2bfloat16(v2 - __bfloat162float(h2));
        }
        const float* g0 = W0 + d * HDIM * (EDIM + 1);   // [64][33]
#pragma unroll 1
        for (int idx = tid; idx < 64 * W0_STRIDE; idx += TPB) {
            int n = idx / W0_STRIDE, k = idx - n * W0_STRIDE;
            float v = (k < 33) ? g0[n * 33 + k] : 0.f;
            __nv_bfloat16 h = __float2bfloat16(v);
            W0hi[idx] = h;
            W0lo[idx] = __float2bfloat16(v - __bfloat162float(h));
        }
        if (tid < 64) {
            sW0x[tid] = g0[tid * 33 + 32];
            sWo[tid]  = Wo[d * 64 + tid];
            sB0[tid]  = b0[d * 64 + tid];
            sB1[tid]  = b1[d * 64 + tid];
            sB2[tid]  = b2[d * 64 + tid];
        }
    }

    // ---- stage A0: row tid = [emb(32) | xt | zeros..47] hi/lo ----
    if (tid < 128) {
        int n    = nbase + tid;
        int bb   = n / LEN;
        int l    = n - bb * LEN;
        int grow = bb * TROW + 2 + l;          // LAGS = 2
        const float4* er = (const float4*)(emb + (size_t)grow * EDIM);
        u32* rh = (u32*)(A0hi + tid * A0_STRIDE);
        u32* rl = (u32*)(A0lo + tid * A0_STRIDE);
#pragma unroll
        for (int k = 0; k < 8; ++k) {
            float4 v = er[k];
            pack_hilo(v.x, v.y, rh[2 * k],     rl[2 * k]);
            pack_hilo(v.z, v.w, rh[2 * k + 1], rl[2 * k + 1]);
        }
        float xt = x[grow * DDIM + d];
        pack_hilo(xt, 0.f, rh[16], rl[16]);
#pragma unroll
        for (int k = 17; k < 24; ++k) { rh[k] = 0u; rl[k] = 0u; }
    }
    __syncthreads();

    const int w    = tid >> 5;
    const int lane = tid & 31;
    const int q    = lane >> 2;       // groupID (row within 8)
    const int r    = lane & 3;        // col-pair selector
    const int R    = 16 * w;          // this warp's tile-local row base
    const float bod = bo[d];

    float c[8][4];
    u32 ah[4][4], al[4][4];
    u32 mask0, mask1, mask2;

    // ================= a-path: layer 0 =================
#pragma unroll
    for (int nt = 0; nt < 8; ++nt)
#pragma unroll
        for (int i = 0; i < 4; ++i) c[nt][i] = 0.f;
    {
        const u32* r0h = (const u32*)(A0hi + (R + q) * A0_STRIDE);
        const u32* r8h = (const u32*)(A0hi + (R + q + 8) * A0_STRIDE);
        const u32* r0l = (const u32*)(A0lo + (R + q) * A0_STRIDE);
        const u32* r8l = (const u32*)(A0lo + (R + q + 8) * A0_STRIDE);
#pragma unroll
        for (int kt = 0; kt < 3; ++kt) {       // k-tile 3 is all zero — skipped
            u32 fh[4], fl[4];
            fh[0] = r0h[8 * kt + r];     fh[1] = r8h[8 * kt + r];
            fh[2] = r0h[8 * kt + r + 4]; fh[3] = r8h[8 * kt + r + 4];
            fl[0] = r0l[8 * kt + r];     fl[1] = r8l[8 * kt + r];
            fl[2] = r0l[8 * kt + r + 4]; fl[3] = r8l[8 * kt + r + 4];
#pragma unroll
            for (int nt = 0; nt < 8; ++nt) {
                const __nv_bfloat16* bh = W0hi + (8 * nt + q) * W0_STRIDE + 16 * kt + 2 * r;
                const __nv_bfloat16* bl = W0lo + (8 * nt + q) * W0_STRIDE + 16 * kt + 2 * r;
                u32 bh0 = *(const u32*)bh, bh1 = *(const u32*)(bh + 8);
                u32 bl0 = *(const u32*)bl, bl1 = *(const u32*)(bl + 8);
                mma16816(c[nt], fh, bh0, bh1);
                mma16816(c[nt], fh, bl0, bl1);
                mma16816(c[nt], fl, bh0, bh1);
            }
        }
    }
    // epilogue 0: bias + gate + record mask0 + build layer-1 A frags
    mask0 = 0;
#pragma unroll
    for (int nt = 0; nt < 8; ++nt) {
        float bz0 = sB0[8 * nt + 2 * r], bz1 = sB0[8 * nt + 2 * r + 1];
        float z0 = c[nt][0] + bz0, z1 = c[nt][1] + bz1;
        float z2 = c[nt][2] + bz0, z3 = c[nt][3] + bz1;
        u32 m = (u32)(z0 < 0.f) | ((u32)(z1 < 0.f) << 1)
              | ((u32)(z2 < 0.f) << 2) | ((u32)(z3 < 0.f) << 3);
        mask0 |= m << (4 * nt);
        float a0 = (z0 < 0.f) ? 0.2f * z0 : z0;
        float a1 = (z1 < 0.f) ? 0.2f * z1 : z1;
        float a2 = (z2 < 0.f) ? 0.2f * z2 : z2;
        float a3 = (z3 < 0.f) ? 0.2f * z3 : z3;
        int kt = nt >> 1, h = (nt & 1) * 2;    // C->A fragment identity
        pack_hilo(a0, a1, ah[kt][h],     al[kt][h]);
        pack_hilo(a2, a3, ah[kt][h + 1], al[kt][h + 1]);
    }

    // ================= a-path: layer 1 =================
    hidden_mma(W1hi, W1lo, q, r, ah, al, c);
    mask1 = 0;
#pragma unroll
    for (int nt = 0; nt < 8; ++nt) {
        float bz0 = sB1[8 * nt + 2 * r], bz1 = sB1[8 * nt + 2 * r + 1];
        float z0 = c[nt][0] + bz0, z1 = c[nt][1] + bz1;
        float z2 = c[nt][2] + bz0, z3 = c[nt][3] + bz1;
        u32 m = (u32)(z0 < 0.f) | ((u32)(z1 < 0.f) << 1)
              | ((u32)(z2 < 0.f) << 2) | ((u32)(z3 < 0.f) << 3);
        mask1 |= m << (4 * nt);
        float a0 = (z0 < 0.f) ? 0.2f * z0 : z0;
        float a1 = (z1 < 0.f) ? 0.2f * z1 : z1;
        float a2 = (z2 < 0.f) ? 0.2f * z2 : z2;
        float a3 = (z3 < 0.f) ? 0.2f * z3 : z3;
        int kt = nt >> 1, h = (nt & 1) * 2;
        pack_hilo(a0, a1, ah[kt][h],     al[kt][h]);
        pack_hilo(a2, a3, ah[kt][h + 1], al[kt][h + 1]);
    }

    // ================= a-path: layer 2 + residual head =================
    hidden_mma(W2hi, W2lo, q, r, ah, al, c);
    mask2 = 0;
    {
        float p0 = 0.f, p1 = 0.f;
#pragma unroll
        for (int nt = 0; nt < 8; ++nt) {
            float bz0 = sB2[8 * nt + 2 * r], bz1 = sB2[8 * nt + 2 * r + 1];
            float wo0 = sWo[8 * nt + 2 * r], wo1 = sWo[8 * nt + 2 * r + 1];
            float z0 = c[nt][0] + bz0, z1 = c[nt][1] + bz1;
            float z2 = c[nt][2] + bz0, z3 = c[nt][3] + bz1;
            u32 m = (u32)(z0 < 0.f) | ((u32)(z1 < 0.f) << 1)
                  | ((u32)(z2 < 0.f) << 2) | ((u32)(z3 < 0.f) << 3);
            mask2 |= m << (4 * nt);
            float a0 = (z0 < 0.f) ? 0.2f * z0 : z0;
            float a1 = (z1 < 0.f) ? 0.2f * z1 : z1;
            float a2 = (z2 < 0.f) ? 0.2f * z2 : z2;
            float a3 = (z3 < 0.f) ? 0.2f * z3 : z3;
            p0 = fmaf(wo0, a0, p0); p0 = fmaf(wo1, a1, p0);
            p1 = fmaf(wo0, a2, p1); p1 = fmaf(wo1, a3, p1);
        }
        p0 += __shfl_xor_sync(0xffffffffu, p0, 1);
        p0 += __shfl_xor_sync(0xffffffffu, p0, 2);
        p1 += __shfl_xor_sync(0xffffffffu, p1, 1);
        p1 += __shfl_xor_sync(0xffffffffu, p1, 2);
        if (r == 0) {
            out[(nbase + R + q) * DDIM + d]     = p0 + bod;
            out[(nbase + R + q + 8) * DDIM + d] = p1 + bod;
        }
    }

    // ================= t-path: t0 = gate0 * W0x (built in C layout) =================
#pragma unroll
    for (int nt = 0; nt < 8; ++nt) {
        float w0v = sW0x[8 * nt + 2 * r], w1v = sW0x[8 * nt + 2 * r + 1];
        u32 m = mask0 >> (4 * nt);
        float t0 = (m & 1u) ? 0.2f * w0v : w0v;
        float t1 = (m & 2u) ? 0.2f * w1v : w1v;
        float t2 = (m & 4u) ? 0.2f * w0v : w0v;
        float t3 = (m & 8u) ? 0.2f * w1v : w1v;
        int kt = nt >> 1, h = (nt & 1) * 2;
        pack_hilo(t0, t1, ah[kt][h],     al[kt][h]);
        pack_hilo(t2, t3, ah[kt][h + 1], al[kt][h + 1]);
    }

    // ================= t-path: layer 1 =================
    hidden_mma(W1hi, W1lo, q, r, ah, al, c);
#pragma unroll
    for (int nt = 0; nt < 8; ++nt) {
        u32 m = mask1 >> (4 * nt);
        float t0 = (m & 1u) ? 0.2f * c[nt][0] : c[nt][0];
        float t1 = (m & 2u) ? 0.2f * c[nt][1] : c[nt][1];
        float t2 = (m & 4u) ? 0.2f * c[nt][2] : c[nt][2];
        float t3 = (m & 8u) ? 0.2f * c[nt][3] : c[nt][3];
        int kt = nt >> 1, h = (nt & 1) * 2;
        pack_hilo(t0, t1, ah[kt][h],     al[kt][h]);
        pack_hilo(t2, t3, ah[kt][h + 1], al[kt][h + 1]);
    }

    // ================= t-path: layer 2 + Jacobian head =================
    hidden_mma(W2hi, W2lo, q, r, ah, al, c);
    {
        float p0 = 0.f, p1 = 0.f;
#pragma unroll
        for (int nt = 0; nt < 8; ++nt) {
            float wo0 = sWo[8 * nt + 2 * r], wo1 = sWo[8 * nt + 2 * r + 1];
            u32 m = mask2 >> (4 * nt);
            float t0 = (m & 1u) ? 0.2f * c[nt][0] : c[nt][0];
            float t1 = (m & 2u) ? 0.2f * c[nt][1] : c[nt][1];
            float t2 = (m & 4u) ? 0.2f * c[nt][2] : c[nt][2];
            float t3 = (m & 8u) ? 0.2f * c[nt][3] : c[nt][3];
            p0 = fmaf(wo0, t0, p0); p0 = fmaf(wo1, t1, p0);
            p1 = fmaf(wo0, t2, p1); p1 = fmaf(wo1, t3, p1);
        }
        p0 += __shfl_xor_sync(0xffffffffu, p0, 1);
        p0 += __shfl_xor_sync(0xffffffffu, p0, 2);
        p1 += __shfl_xor_sync(0xffffffffu, p1, 1);
        p1 += __shfl_xor_sync(0xffffffffu, p1, 2);
        if (r == 0) {
            g_dj[d * NSAMP + nbase + R + q]     = logf(fabsf(p0));
            g_dj[d * NSAMP + nbase + R + q + 8] = logf(fabsf(p1));
        }
    }
}

extern "C" __global__ void __launch_bounds__(256)
reduce_logdet_kernel(float* __restrict__ out)
{
    int n = blockIdx.x * 256 + threadIdx.x;
    if (n < NSAMP) {
        float s = 0.f;
#pragma unroll
        for (int d = 0; d < DDIM; ++d) s += g_dj[d * NSAMP + n];
        out[NSAMP * DDIM + n] = s;   // logdet region after residuals
    }
}

extern "C" void kernel_launch(void* const* d_in, const int* in_sizes, int n_in,
                              void* d_out, int out_size)
{
    const float* x   = (const float*)d_in[0];
    const float* emb = (const float*)d_in[1];
    const float* W0  = (const float*)d_in[2];
    const float* b0  = (const float*)d_in[3];
    const float* W1  = (const float*)d_in[4];
    const float* b1  = (const float*)d_in[5];
    const float* W2  = (const float*)d_in[6];
    const float* b2  = (const float*)d_in[7];
    const float* Wo  = (const float*)d_in[8];
    const float* bo  = (const float*)d_in[9];
    float* out = (float*)d_out;

    // Idempotent opt-in for >48KB dynamic smem (capture-safe, not a stream op).
    cudaFuncSetAttribute(mlp_mma_kernel,
                         cudaFuncAttributeMaxDynamicSharedMemorySize, SMEM_BYTES);

    dim3 grid(NSAMP / 128, DDIM);   // (250, 16)
    mlp_mma_kernel<<<grid, TPB, SMEM_BYTES>>>(x, emb, W0, b0, W1, b1, W2, b2,
                                              Wo, bo, out);
    reduce_logdet_kernel<<<(NSAMP + 255) / 256, 256>>>(out);
}

// round 16
// speedup vs baseline: 3.4344x; 1.0065x over previous
#include <cuda_runtime.h>
#include <cuda_bf16.h>

// Problem constants
#define TPB    256        // 8 warps; one 16-row m-tile per warp; 128 samples/CTA
#define NSAMP  32000      // B*length = 32*1000
#define LEN    1000
#define TROW   1002
#define DDIM   16
#define EDIM   32
#define HDIM   64

typedef unsigned int u32;
typedef unsigned long long u64;

// Scratch for per-(d, n) log|dJ| — deterministic reduction in a second kernel.
__device__ float g_dj[DDIM * NSAMP];

// ---------------- smem layout (byte offsets) ----------------
// A0  [128 rows][20 u64]  interleaved (hi-pair u32, lo-pair u32) per k-pair
// W0,W1,W2 [64 rows][34 u64] interleaved hi/lo, row stride 272B
// f32: W0x[64], Wo[64], b0[64], b1[64], b2[64], xt[128]
#define OFF_A0   0
#define OFF_W0   20480
#define OFF_W1   37888
#define OFF_W2   55296
#define OFF_F32  72704
#define SMEM_BYTES 74496   // x2 CTAs = 148992 <= 228KB

#define A0_STRIDE64 20     // u64/row: (4q+r) mod 16 -> exact 2-way banks
#define W_STRIDE64  34     // u64/row: (2q+r) mod 16 -> max 2-way banks
#define A0_STRIDE16 80     // bf16 units per row (20*4)
#define W_STRIDE16  136    // bf16 units per row (34*4)

// pack two f32 into bf16x2 (v0 -> low half, v1 -> high half)
__device__ __forceinline__ u32 cvtbf2(float v0, float v1) {
    u32 v; asm("cvt.rn.bf16x2.f32 %0, %1, %2;" : "=r"(v) : "f"(v1), "f"(v0)); return v;
}
__device__ __forceinline__ float lo_f(u32 p) { return __uint_as_float(p << 16); }
__device__ __forceinline__ float hi_f(u32 p) { return __uint_as_float(p & 0xffff0000u); }

// split v0,v1 into bf16 hi pair + bf16 lo (residual) pair
__device__ __forceinline__ void pack_hilo(float v0, float v1, u32& h, u32& l) {
    h = cvtbf2(v0, v1);
    l = cvtbf2(v0 - lo_f(h), v1 - hi_f(h));
}

__device__ __forceinline__ void mma16816(float c[4], const u32 a[4], u32 b0, u32 b1) {
    asm volatile(
        "mma.sync.aligned.m16n8k16.row.col.f32.bf16.bf16.f32 "
        "{%0,%1,%2,%3}, {%4,%5,%6,%7}, {%8,%9}, {%0,%1,%2,%3};"
        : "+f"(c[0]), "+f"(c[1]), "+f"(c[2]), "+f"(c[3])
        : "r"(a[0]), "r"(a[1]), "r"(a[2]), "r"(a[3]), "r"(b0), "r"(b1));
}

// One layer, K = 16*KT: C[8 nt][4] = (Ahi+Alo) @ (Whi+Wlo), 3-way split.
// Wp: interleaved u64 view; each u64 = (hi-pair lo32, lo-pair hi32).
template <int KT>
__device__ __forceinline__ void layer_mma(const u64* __restrict__ Wp, int q, int r,
                                          const u32 ah[4][4], const u32 al[4][4],
                                          float c[8][4])
{
#pragma unroll
    for (int nt = 0; nt < 8; ++nt)
#pragma unroll
        for (int i = 0; i < 4; ++i) c[nt][i] = 0.f;
#pragma unroll
    for (int kt = 0; kt < KT; ++kt) {
#pragma unroll
        for (int nt = 0; nt < 8; ++nt) {
            const u64* b = Wp + (8 * nt + q) * W_STRIDE64 + 8 * kt + r;
            u64 v0 = b[0];
            u64 v1 = b[4];
            u32 bh0 = (u32)v0, bl0 = (u32)(v0 >> 32);
            u32 bh1 = (u32)v1, bl1 = (u32)(v1 >> 32);
            mma16816(c[nt], ah[kt], bh0, bh1);
            mma16816(c[nt], ah[kt], bl0, bl1);
            mma16816(c[nt], al[kt], bh0, bh1);
        }
    }
}

extern "C" __global__ void __launch_bounds__(TPB, 2)
mlp_mma_kernel(const float* __restrict__ x,  const float* __restrict__ emb,
               const float* __restrict__ W0, const float* __restrict__ b0,
               const float* __restrict__ W1, const float* __restrict__ b1,
               const float* __restrict__ W2, const float* __restrict__ b2,
               const float* __restrict__ Wo, const float* __restrict__ bo,
               float* __restrict__ out)
{
    extern __shared__ char smraw[];
    __nv_bfloat16* A0i = (__nv_bfloat16*)(smraw + OFF_A0);
    __nv_bfloat16* W0i = (__nv_bfloat16*)(smraw + OFF_W0);
    __nv_bfloat16* W1i = (__nv_bfloat16*)(smraw + OFF_W1);
    __nv_bfloat16* W2i = (__nv_bfloat16*)(smraw + OFF_W2);
    float* sF   = (float*)(smraw + OFF_F32);
    float* sW0x = sF;
    float* sWo  = sF + 64;
    float* sB0  = sF + 128;
    float* sB1  = sF + 192;
    float* sB2  = sF + 256;
    float* sXT  = sF + 320;      // [128]

    const int tid   = threadIdx.x;
    const int d     = blockIdx.y;
    const int nbase = blockIdx.x * 128;

    // ---- stage weights: interleaved (hi-pair, lo-pair) u32s, [n][k] ----
    {
        const float* g1 = W1 + d * 4096;
        const float* g2 = W2 + d * 4096;
#pragma unroll 1
        for (int idx = tid; idx < 4096; idx += TPB) {
            int n = idx >> 6, k = idx & 63;
            int o = n * W_STRIDE16 + (k >> 1) * 4 + (k & 1);
            float v1 = g1[idx];
            __nv_bfloat16 h1 = __float2bfloat16(v1);
            W1i[o]     = h1;
            W1i[o + 2] = __float2bfloat16(v1 - __bfloat162float(h1));
            float v2 = g2[idx];
            __nv_bfloat16 h2 = __float2bfloat16(v2);
            W2i[o]     = h2;
            W2i[o + 2] = __float2bfloat16(v2 - __bfloat162float(h2));
        }
        const float* g0 = W0 + d * HDIM * (EDIM + 1);   // [64][33]
#pragma unroll 1
        for (int idx = tid; idx < 64 * 33; idx += TPB) {
            int n = idx / 33, k = idx - n * 33;
            float v = g0[idx];
            if (k == 32) {
                sW0x[n] = v;
            } else {
                int o = n * W_STRIDE16 + (k >> 1) * 4 + (k & 1);
                __nv_bfloat16 h = __float2bfloat16(v);
                W0i[o]     = h;
                W0i[o + 2] = __float2bfloat16(v - __bfloat162float(h));
            }
        }
        if (tid < 64) {
            sWo[tid]  = Wo[d * 64 + tid];
            sB0[tid]  = b0[d * 64 + tid];
            sB1[tid]  = b1[d * 64 + tid];
            sB2[tid]  = b2[d * 64 + tid];
        }
    }

    // ---- stage A0 (emb only, k 0..31 interleaved) + xt to f32 smem ----
    if (tid < 128) {
        int n    = nbase + tid;
        int bb   = n / LEN;
        int l    = n - bb * LEN;
        int grow = bb * TROW + 2 + l;          // LAGS = 2
        const float4* er = (const float4*)(emb + (size_t)grow * EDIM);
        u32* rw = (u32*)(A0i + tid * A0_STRIDE16);
#pragma unroll
        for (int j = 0; j < 8; ++j) {
            float4 v = er[j];
            pack_hilo(v.x, v.y, rw[4 * j],     rw[4 * j + 1]);
            pack_hilo(v.z, v.w, rw[4 * j + 2], rw[4 * j + 3]);
        }
        sXT[tid] = x[grow * DDIM + d];
    }
    __syncthreads();

    const int w    = tid >> 5;
    const int lane = tid & 31;
    const int q    = lane >> 2;       // groupID (row within 8)
    const int r    = lane & 3;        // col-pair selector
    const int R    = 16 * w;          // this warp's tile-local row base
    const float bod = bo[d];

    const u64* W0p = (const u64*)W0i;
    const u64* W1p = (const u64*)W1i;
    const u64* W2p = (const u64*)W2i;

    float c[8][4];
    u32 ah[4][4], al[4][4];
    u32 mask0, mask1, mask2;

    // ---- load layer-0 A fragments (kt 0..1 — emb is K=32) ----
    {
        const u64* r0 = (const u64*)(A0i + (R + q) * A0_STRIDE16);
        const u64* r8 = (const u64*)(A0i + (R + q + 8) * A0_STRIDE16);
#pragma unroll
        for (int kt = 0; kt < 2; ++kt) {
            u64 v0 = r0[8 * kt + r];
            u64 v1 = r8[8 * kt + r];
            u64 v2 = r0[8 * kt + r + 4];
            u64 v3 = r8[8 * kt + r + 4];
            ah[kt][0] = (u32)v0; al[kt][0] = (u32)(v0 >> 32);
            ah[kt][1] = (u32)v1; al[kt][1] = (u32)(v1 >> 32);
            ah[kt][2] = (u32)v2; al[kt][2] = (u32)(v2 >> 32);
            ah[kt][3] = (u32)v3; al[kt][3] = (u32)(v3 >> 32);
        }
    }

    const float xtq  = sXT[R + q];
    const float xtq8 = sXT[R + q + 8];

    // ================= a-path: layer 0 (emb MMA + exact xt FFMA) =================
    layer_mma<2>(W0p, q, r, ah, al, c);
    mask0 = 0;
#pragma unroll
    for (int nt = 0; nt < 8; ++nt) {
        float bz0 = sB0[8 * nt + 2 * r], bz1 = sB0[8 * nt + 2 * r + 1];
        float w0v = sW0x[8 * nt + 2 * r], w1v = sW0x[8 * nt + 2 * r + 1];
        float z0 = fmaf(w0v, xtq,  c[nt][0] + bz0);
        float z1 = fmaf(w1v, xtq,  c[nt][1] + bz1);
        float z2 = fmaf(w0v, xtq8, c[nt][2] + bz0);
        float z3 = fmaf(w1v, xtq8, c[nt][3] + bz1);
        u32 m = (u32)(z0 < 0.f) | ((u32)(z1 < 0.f) << 1)
              | ((u32)(z2 < 0.f) << 2) | ((u32)(z3 < 0.f) << 3);
        mask0 |= m << (4 * nt);
        float a0 = (z0 < 0.f) ? 0.2f * z0 : z0;
        float a1 = (z1 < 0.f) ? 0.2f * z1 : z1;
        float a2 = (z2 < 0.f) ? 0.2f * z2 : z2;
        float a3 = (z3 < 0.f) ? 0.2f * z3 : z3;
        int kt = nt >> 1, h = (nt & 1) * 2;    // C->A fragment identity
        pack_hilo(a0, a1, ah[kt][h],     al[kt][h]);
        pack_hilo(a2, a3, ah[kt][h + 1], al[kt][h + 1]);
    }

    // ================= a-path: layer 1 =================
    layer_mma<4>(W1p, q, r, ah, al, c);
    mask1 = 0;
#pragma unroll
    for (int nt = 0; nt < 8; ++nt) {
        float bz0 = sB1[8 * nt + 2 * r], bz1 = sB1[8 * nt + 2 * r + 1];
        float z0 = c[nt][0] + bz0, z1 = c[nt][1] + bz1;
        float z2 = c[nt][2] + bz0, z3 = c[nt][3] + bz1;
        u32 m = (u32)(z0 < 0.f) | ((u32)(z1 < 0.f) << 1)
              | ((u32)(z2 < 0.f) << 2) | ((u32)(z3 < 0.f) << 3);
        mask1 |= m << (4 * nt);
        float a0 = (z0 < 0.f) ? 0.2f * z0 : z0;
        float a1 = (z1 < 0.f) ? 0.2f * z1 : z1;
        float a2 = (z2 < 0.f) ? 0.2f * z2 : z2;
        float a3 = (z3 < 0.f) ? 0.2f * z3 : z3;
        int kt = nt >> 1, h = (nt & 1) * 2;
        pack_hilo(a0, a1, ah[kt][h],     al[kt][h]);
        pack_hilo(a2, a3, ah[kt][h + 1], al[kt][h + 1]);
    }

    // ================= a-path: layer 2 + residual head =================
    layer_mma<4>(W2p, q, r, ah, al, c);
    mask2 = 0;
    {
        float p0 = 0.f, p1 = 0.f;
#pragma unroll
        for (int nt = 0; nt < 8; ++nt) {
            float bz0 = sB2[8 * nt + 2 * r], bz1 = sB2[8 * nt + 2 * r + 1];
            float wo0 = sWo[8 * nt + 2 * r], wo1 = sWo[8 * nt + 2 * r + 1];
            float z0 = c[nt][0] + bz0, z1 = c[nt][1] + bz1;
            float z2 = c[nt][2] + bz0, z3 = c[nt][3] + bz1;
            u32 m = (u32)(z0 < 0.f) | ((u32)(z1 < 0.f) << 1)
                  | ((u32)(z2 < 0.f) << 2) | ((u32)(z3 < 0.f) << 3);
            mask2 |= m << (4 * nt);
            float a0 = (z0 < 0.f) ? 0.2f * z0 : z0;
            float a1 = (z1 < 0.f) ? 0.2f * z1 : z1;
            float a2 = (z2 < 0.f) ? 0.2f * z2 : z2;
            float a3 = (z3 < 0.f) ? 0.2f * z3 : z3;
            p0 = fmaf(wo0, a0, p0); p0 = fmaf(wo1, a1, p0);
            p1 = fmaf(wo0, a2, p1); p1 = fmaf(wo1, a3, p1);
        }
        p0 += __shfl_xor_sync(0xffffffffu, p0, 1);
        p0 += __shfl_xor_sync(0xffffffffu, p0, 2);
        p1 += __shfl_xor_sync(0xffffffffu, p1, 1);
        p1 += __shfl_xor_sync(0xffffffffu, p1, 2);
        if (r == 0) {
            out[(nbase + R + q) * DDIM + d]     = p0 + bod;
            out[(nbase + R + q + 8) * DDIM + d] = p1 + bod;
        }
    }

    // ================= t-path: t0 = gate0 * W0x (built in C layout) =================
#pragma unroll
    for (int nt = 0; nt < 8; ++nt) {
        float w0v = sW0x[8 * nt + 2 * r], w1v = sW0x[8 * nt + 2 * r + 1];
        u32 m = mask0 >> (4 * nt);
        float t0 = (m & 1u) ? 0.2f * w0v : w0v;
        float t1 = (m & 2u) ? 0.2f * w1v : w1v;
        float t2 = (m & 4u) ? 0.2f * w0v : w0v;
        float t3 = (m & 8u) ? 0.2f * w1v : w1v;
        int kt = nt >> 1, h = (nt & 1) * 2;
        pack_hilo(t0, t1, ah[kt][h],     al[kt][h]);
        pack_hilo(t2, t3, ah[kt][h + 1], al[kt][h + 1]);
    }

    // ================= t-path: layer 1 =================
    layer_mma<4>(W1p, q, r, ah, al, c);
#pragma unroll
    for (int nt = 0; nt < 8; ++nt) {
        u32 m = mask1 >> (4 * nt);
        float t0 = (m & 1u) ? 0.2f * c[nt][0] : c[nt][0];
        float t1 = (m & 2u) ? 0.2f * c[nt][1] : c[nt][1];
        float t2 = (m & 4u) ? 0.2f * c[nt][2] : c[nt][2];
        float t3 = (m & 8u) ? 0.2f * c[nt][3] : c[nt][3];
        int kt = nt >> 1, h = (nt & 1) * 2;
        pack_hilo(t0, t1, ah[kt][h],     al[kt][h]);
        pack_hilo(t2, t3, ah[kt][h + 1], al[kt][h + 1]);
    }

    // ================= t-path: layer 2 + Jacobian head =================
    layer_mma<4>(W2p, q, r, ah, al, c);
    {
        float p0 = 0.f, p1 = 0.f;
#pragma unroll
        for (int nt = 0; nt < 8; ++nt) {
            float wo0 = sWo[8 * nt + 2 * r], wo1 = sWo[8 * nt + 2 * r + 1];
            u32 m = mask2 >> (4 * nt);
            float t0 = (m & 1u) ? 0.2f * c[nt][0] : c[nt][0];
            float t1 = (m & 2u) ? 0.2f * c[nt][1] : c[nt][1];
            float t2 = (m & 4u) ? 0.2f * c[nt][2] : c[nt][2];
            float t3 = (m & 8u) ? 0.2f * c[nt][3] : c[nt][3];
            p0 = fmaf(wo0, t0, p0); p0 = fmaf(wo1, t1, p0);
            p1 = fmaf(wo0, t2, p1); p1 = fmaf(wo1, t3, p1);
        }
        p0 += __shfl_xor_sync(0xffffffffu, p0, 1);
        p0 += __shfl_xor_sync(0xffffffffu, p0, 2);
        p1 += __shfl_xor_sync(0xffffffffu, p1, 1);
        p1 += __shfl_xor_sync(0xffffffffu, p1, 2);
        if (r == 0) {
            g_dj[d * NSAMP + nbase + R + q]     = logf(fabsf(p0));
            g_dj[d * NSAMP + nbase + R + q + 8] = logf(fabsf(p1));
        }
    }
}

extern "C" __global__ void __launch_bounds__(256)
reduce_logdet_kernel(float* __restrict__ out)
{
    int n = blockIdx.x * 256 + threadIdx.x;
    if (n < NSAMP) {
        float s = 0.f;
#pragma unroll
        for (int d = 0; d < DDIM; ++d) s += g_dj[d * NSAMP + n];
        out[NSAMP * DDIM + n] = s;   // logdet region after residuals
    }
}

extern "C" void kernel_launch(void* const* d_in, const int* in_sizes, int n_in,
                              void* d_out, int out_size)
{
    const float* x   = (const float*)d_in[0];
    const float* emb = (const float*)d_in[1];
    const float* W0  = (const float*)d_in[2];
    const float* b0  = (const float*)d_in[3];
    const float* W1  = (const float*)d_in[4];
    const float* b1  = (const float*)d_in[5];
    const float* W2  = (const float*)d_in[6];
    const float* b2  = (const float*)d_in[7];
    const float* Wo  = (const float*)d_in[8];
    const float* bo  = (const float*)d_in[9];
    float* out = (float*)d_out;

    // Idempotent opt-in for >48KB dynamic smem (capture-safe, not a stream op).
    cudaFuncSetAttribute(mlp_mma_kernel,
                         cudaFuncAttributeMaxDynamicSharedMemorySize, SMEM_BYTES);

    dim3 grid(NSAMP / 128, DDIM);   // (250, 16)
    mlp_mma_kernel<<<grid, TPB, SMEM_BYTES>>>(x, emb, W0, b0, W1, b1, W2, b2,
                                              Wo, bo, out);
    reduce_logdet_kernel<<<(NSAMP + 255) / 256, 256>>>(out);
}